// round 10
// baseline (speedup 1.0000x reference)
#include <cuda_runtime.h>

// Heston Monte Carlo, 65536 paths x 512 steps.
// d_in[0] = Z_vol [65536, 512, 2] f32 (channel-interleaved), d_in[1] = Z_price [65536, 512] f32
// d_out = concat(S, V), each [65536, 513] f32.

namespace {

constexpr int BATCH  = 65536;
constexpr int NSTEPS = 512;
constexpr int ROWLEN = NSTEPS + 1;     // 513
constexpr int BLOCK  = 64;             // paths per block
constexpr int CHUNK  = 16;             // time steps per staged chunk
constexpr int NCHUNK = NSTEPS / CHUNK; // 32
constexpr int NBUF   = 3;              // chunk ring: 1 consuming + 2 in flight

constexpr float DT       = 1.0f / 512.0f;
constexpr float SQRT_DT  = 0.044194173824159216f;  // sqrt(1/512)
constexpr float V0C      = 0.055225f;              // 0.235^2
constexpr float S0F      = 100.0f;

constexpr float KTDT  = 1.0f * 0.04f * DT;         // KAPPA*THETA*dt
constexpr float NKDT  = -1.0f * DT;                // -KAPPA*dt
constexpr float CSV   = 2.0f * SQRT_DT;            // SIGMA_V*sqrt(dt)
constexpr float RSD   = -0.7f * SQRT_DT;           // RHO*sqrt(dt)
constexpr float RPSD  = 0.7141428428542850f * SQRT_DT; // sqrt(1-rho^2)*sqrt(dt)
constexpr float NHDT  = -0.5f * DT;
constexpr float LOG2E   = 1.4426950408889634f;
constexpr float LOG2S0  = 6.6438561897747395f;     // log2(100)

}  // namespace

__device__ __forceinline__ float sqrt_approx(float x) {
    float r; asm("sqrt.approx.f32 %0, %1;" : "=f"(r) : "f"(x)); return r;
}
__device__ __forceinline__ float ex2_approx(float x) {
    float r; asm("ex2.approx.f32 %0, %1;" : "=f"(r) : "f"(x)); return r;
}
__device__ __forceinline__ void cp16(unsigned dst, const void* src) {
    asm volatile("cp.async.cg.shared.global [%0], [%1], 16;\n"
                 :: "r"(dst), "l"(src) : "memory");
}
__device__ __forceinline__ void cp_commit() {
    asm volatile("cp.async.commit_group;\n" ::: "memory");
}
__device__ __forceinline__ void cp_wait2() {
    asm volatile("cp.async.wait_group 2;\n" ::: "memory");
}

__global__ void __launch_bounds__(BLOCK, 6)
heston_kernel(const float* __restrict__ Zv,
              const float* __restrict__ Zp,
              float* __restrict__ out)
{
    // Zv chunks: 128B rows, slot swizzle q^(row&7). Compute/writeout LDS.128 is
    // phase-conflict-free. Reused in place for results (S0,V0,S1,V1) per 16B.
    __shared__ float4 zv[NBUF][BLOCK][8];
    // Zp chunks: 64B rows, slot swizzle q^((row>>2)&3); cp.async dst 16B-aligned.
    __shared__ float4 zp[NBUF][BLOCK][4];

    const int tid = threadIdx.x;
    const int b0  = blockIdx.x * BLOCK;
    const int r7  = tid & 7;
    const int r23 = (tid >> 2) & 3;

    float* __restrict__ Sout = out;
    float* __restrict__ Vout = out + (size_t)BATCH * ROWLEN;

    // Column 0: S = S0, V = V0.
    {
        const size_t g = (size_t)(b0 + tid) * ROWLEN;
        Sout[g] = S0F;
        Vout[g] = V0C;
    }

    const char* zv_gbase = (const char*)Zv + (size_t)b0 * (2 * NSTEPS * 4);
    const char* zp_gbase = (const char*)Zp + (size_t)b0 * (NSTEPS * 4);

    // Stage Zv chunk (64 rows x 128B = 8 cp/thread) + Zp chunk (64 rows x 64B =
    // 4 cp/thread) into ring buffer bi_, ONE commit group per chunk.
#define STAGE(c_, bi_)                                                             \
    do {                                                                           \
        _Pragma("unroll")                                                          \
        for (int k = 0; k < 8; ++k) {                                              \
            const int idx = tid + BLOCK * k;      /* 0..511 */                     \
            const int row = idx >> 3;                                              \
            const int q   = idx & 7;                                               \
            cp16((unsigned)__cvta_generic_to_shared(&zv[bi_][row][q ^ (row & 7)]), \
                 zv_gbase + (size_t)row * (2 * NSTEPS * 4) + (size_t)(c_) * 128 + q * 16); \
        }                                                                          \
        _Pragma("unroll")                                                          \
        for (int k = 0; k < 4; ++k) {                                              \
            const int idx = tid + BLOCK * k;      /* 0..255 */                     \
            const int row = idx >> 2;                                              \
            const int q   = idx & 3;                                               \
            cp16((unsigned)__cvta_generic_to_shared(&zp[bi_][row][q ^ ((row >> 2) & 3)]), \
                 zp_gbase + (size_t)row * (NSTEPS * 4) + (size_t)(c_) * 64 + q * 16); \
        }                                                                          \
        cp_commit();                                                               \
    } while (0)

    // ---- prologue: chunks 0..2 in flight (groups 0..2) ----
    STAGE(0, 0);
    STAGE(1, 1);
    STAGE(2, 2);

    float V    = V0C;
    float logS = 0.0f;
    int   p    = 0;   // ring position = c % NBUF

    for (int c = 0; c < NCHUNK; ++c) {
        cp_wait2();          // group for chunk c done (c+1, c+2 still flying)
        __syncthreads();     // visible to whole block

        // ---- 16 steps; results overwrite the consumed zv chunk in place ----
        const float* zprow = (const float*)&zp[p][tid][0];
#pragma unroll
        for (int j2 = 0; j2 < 8; ++j2) {
            const int slot = j2 ^ r7;
            const float4 zz = zv[p][tid][slot];        // (zv_{2j2}, ch1, zv_{2j2+1}, ch1)
            const int zslot = (j2 >> 1) ^ r23;
            const float2 zpp = *reinterpret_cast<const float2*>(
                zprow + 4 * zslot + 2 * (j2 & 1));     // (zp_{2j2}, zp_{2j2+1})
            float4 res;

            {   // step 2*j2
                const float Vpos = fmaxf(V, 0.0f);
                const float sq   = sqrt_approx(Vpos);
                float Vn = fmaf(NKDT, Vpos, V + KTDT);
                Vn = fmaf(CSV * sq, zz.x, Vn);
                Vn = fmaxf(Vn, 0.0f);
                const float dB = fmaf(RSD, zz.x, RPSD * zpp.x);
                logS = fmaf(sq, dB, fmaf(NHDT, Vpos, logS));
                res.x = ex2_approx(fmaf(logS, LOG2E, LOG2S0));  // S after step 2j2
                res.y = Vn;
                V = Vn;
            }
            {   // step 2*j2 + 1
                const float Vpos = fmaxf(V, 0.0f);
                const float sq   = sqrt_approx(Vpos);
                float Vn = fmaf(NKDT, Vpos, V + KTDT);
                Vn = fmaf(CSV * sq, zz.z, Vn);
                Vn = fmaxf(Vn, 0.0f);
                const float dB = fmaf(RSD, zz.z, RPSD * zpp.y);
                logS = fmaf(sq, dB, fmaf(NHDT, Vpos, logS));
                res.z = ex2_approx(fmaf(logS, LOG2E, LOG2S0));  // S after step 2j2+1
                res.w = Vn;
                V = Vn;
            }
            zv[p][tid][slot] = res;   // same-thread in-place overwrite: safe
        }
        __syncthreads();

        // ---- cooperative write-out ----
        {
            const int t0 = c * CHUNK;
#pragma unroll
            for (int k = 0; k < 8; ++k) {
                const int idx = tid + BLOCK * k;      // 0..511
                const int row = idx >> 3;
                const int l   = idx & 7;
                const float4 r = zv[p][row][l ^ (row & 7)];
                const size_t g = (size_t)(b0 + row) * ROWLEN + (t0 + 1 + 2 * l);
                Sout[g]     = r.x;
                Sout[g + 1] = r.z;
                Vout[g]     = r.y;
                Vout[g + 1] = r.w;
            }
        }
        __syncthreads();     // ring slot p fully drained before restage

        // restage chunk c+3 into the freed slot; exactly one commit per
        // iteration keeps group count aligned with c (wait_group 2 stays valid)
        if (c + 3 < NCHUNK) STAGE(c + 3, p);
        else                cp_commit();

        p = (p == NBUF - 1) ? 0 : p + 1;
    }
#undef STAGE
}

extern "C" void kernel_launch(void* const* d_in, const int* in_sizes, int n_in,
                              void* d_out, int out_size) {
    (void)in_sizes; (void)n_in; (void)out_size;
    heston_kernel<<<BATCH / BLOCK, BLOCK>>>(
        (const float*)d_in[0], (const float*)d_in[1], (float*)d_out);
}

// round 13
// speedup vs baseline: 1.4529x; 1.4529x over previous
#include <cuda_runtime.h>

// Heston Monte Carlo, 65536 paths x 512 steps.
// d_in[0] = Z_vol [65536, 512, 2] f32 (channel-interleaved), d_in[1] = Z_price [65536, 512] f32
// d_out = concat(S, V), each [65536, 513] f32.

namespace {

constexpr int BATCH  = 65536;
constexpr int NSTEPS = 512;
constexpr int ROWLEN = NSTEPS + 1;     // 513
constexpr int BLOCK  = 64;             // paths per block
constexpr int CHUNK  = 32;             // time steps per staged chunk (256B Zv runs)
constexpr int NCHUNK = NSTEPS / CHUNK; // 16

constexpr float DT       = 1.0f / 512.0f;
constexpr float SQRT_DT  = 0.044194173824159216f;  // sqrt(1/512)
constexpr float V0C      = 0.055225f;              // 0.235^2
constexpr float S0F      = 100.0f;

constexpr float KTDT  = 1.0f * 0.04f * DT;         // KAPPA*THETA*dt
constexpr float NKDT  = -1.0f * DT;                // -KAPPA*dt
constexpr float CSV   = 2.0f * SQRT_DT;            // SIGMA_V*sqrt(dt)
constexpr float RSD   = -0.7f * SQRT_DT;           // RHO*sqrt(dt)
constexpr float RPSD  = 0.7141428428542850f * SQRT_DT; // sqrt(1-rho^2)*sqrt(dt)
constexpr float NHDT  = -0.5f * DT;
constexpr float LOG2E   = 1.4426950408889634f;
constexpr float LOG2S0  = 6.6438561897747395f;     // log2(100)

}  // namespace

__device__ __forceinline__ float sqrt_approx(float x) {
    float r; asm("sqrt.approx.f32 %0, %1;" : "=f"(r) : "f"(x)); return r;
}
__device__ __forceinline__ float ex2_approx(float x) {
    float r; asm("ex2.approx.f32 %0, %1;" : "=f"(r) : "f"(x)); return r;
}
__device__ __forceinline__ void cp16(unsigned dst, const void* src) {
    asm volatile("cp.async.cg.shared.global [%0], [%1], 16;\n"
                 :: "r"(dst), "l"(src) : "memory");
}
__device__ __forceinline__ void cp_commit() {
    asm volatile("cp.async.commit_group;\n" ::: "memory");
}
__device__ __forceinline__ void cp_wait1() {
    asm volatile("cp.async.wait_group 1;\n" ::: "memory");
}
__device__ __forceinline__ void stcs(float* p, float v) {
    asm volatile("st.global.cs.f32 [%0], %1;\n" :: "l"(p), "f"(v) : "memory");
}

__global__ void __launch_bounds__(BLOCK)
heston_kernel(const float* __restrict__ Zv,
              const float* __restrict__ Zp,
              float* __restrict__ out)
{
    // Zv chunks: 256B rows (16 float4 slots), slot swizzle q^(row&7) (low 3
    // bits) -> compute/writeout LDS.128 conflict-free per 8-lane phase.
    // Reused in place for results (S0,V0,S1,V1) per 16B slot.
    __shared__ float4 zv[2][BLOCK][16];
    // Zp chunks: 128B rows (8 float4), natural layout (residual LDS.64
    // conflicts are negligible). cp.async dst 16B-aligned.
    __shared__ float4 zp[2][BLOCK][8];
    // Total static smem: 32KB + 16KB = 48KB -> 4 blocks/SM.

    const int tid = threadIdx.x;
    const int b0  = blockIdx.x * BLOCK;
    const int r7  = tid & 7;

    float* __restrict__ Sout = out;
    float* __restrict__ Vout = out + (size_t)BATCH * ROWLEN;

    // Column 0: S = S0, V = V0.
    {
        const size_t g = (size_t)(b0 + tid) * ROWLEN;
        stcs(&Sout[g], S0F);
        stcs(&Vout[g], V0C);
    }

    const char* zv_gbase = (const char*)Zv + (size_t)b0 * (2 * NSTEPS * 4);
    const char* zp_gbase = (const char*)Zp + (size_t)b0 * (NSTEPS * 4);

    // Stage Zv chunk (64 rows x 256B = 16 cp/thread) + Zp chunk (64 rows x
    // 128B = 8 cp/thread) into buffer bi_, ONE commit group per chunk.
#define STAGE(c_, bi_)                                                             \
    do {                                                                           \
        _Pragma("unroll")                                                          \
        for (int k = 0; k < 16; ++k) {                                             \
            const int idx = tid + BLOCK * k;      /* 0..1023 */                    \
            const int row = idx >> 4;                                              \
            const int q   = idx & 15;                                              \
            cp16((unsigned)__cvta_generic_to_shared(&zv[bi_][row][q ^ (row & 7)]), \
                 zv_gbase + (size_t)row * (2 * NSTEPS * 4) + (size_t)(c_) * (CHUNK * 8) + q * 16); \
        }                                                                          \
        _Pragma("unroll")                                                          \
        for (int k = 0; k < 8; ++k) {                                              \
            const int idx = tid + BLOCK * k;      /* 0..511 */                     \
            const int row = idx >> 3;                                              \
            const int q   = idx & 7;                                               \
            cp16((unsigned)__cvta_generic_to_shared(&zp[bi_][row][q]),             \
                 zp_gbase + (size_t)row * (NSTEPS * 4) + (size_t)(c_) * (CHUNK * 4) + q * 16); \
        }                                                                          \
        cp_commit();                                                               \
    } while (0)

    // ---- prologue: chunks 0 and 1 in flight (groups 0,1) ----
    STAGE(0, 0);
    STAGE(1, 1);

    float V    = V0C;
    float logS = 0.0f;

    for (int c = 0; c < NCHUNK; ++c) {
        const int p = c & 1;

        cp_wait1();          // group for chunk c done (c+1 may still fly)
        __syncthreads();     // visible to whole block

        // ---- 32 steps; results overwrite the consumed zv chunk in place ----
        const float* zprow = (const float*)&zp[p][tid][0];
#pragma unroll
        for (int j2 = 0; j2 < 16; ++j2) {
            const int slot = j2 ^ r7;                  // flips low 3 bits only
            const float4 zz = zv[p][tid][slot];        // (zv_{2j2}, ch1, zv_{2j2+1}, ch1)
            const float2 zpp = *reinterpret_cast<const float2*>(zprow + 2 * j2);
            float4 res;

            {   // step 2*j2
                const float Vpos = fmaxf(V, 0.0f);
                const float sq   = sqrt_approx(Vpos);
                float Vn = fmaf(NKDT, Vpos, V + KTDT);
                Vn = fmaf(CSV * sq, zz.x, Vn);
                Vn = fmaxf(Vn, 0.0f);
                const float dB = fmaf(RSD, zz.x, RPSD * zpp.x);
                logS = fmaf(sq, dB, fmaf(NHDT, Vpos, logS));
                res.x = ex2_approx(fmaf(logS, LOG2E, LOG2S0));  // S after step 2j2
                res.y = Vn;
                V = Vn;
            }
            {   // step 2*j2 + 1
                const float Vpos = fmaxf(V, 0.0f);
                const float sq   = sqrt_approx(Vpos);
                float Vn = fmaf(NKDT, Vpos, V + KTDT);
                Vn = fmaf(CSV * sq, zz.z, Vn);
                Vn = fmaxf(Vn, 0.0f);
                const float dB = fmaf(RSD, zz.z, RPSD * zpp.y);
                logS = fmaf(sq, dB, fmaf(NHDT, Vpos, logS));
                res.z = ex2_approx(fmaf(logS, LOG2E, LOG2S0));  // S after step 2j2+1
                res.w = Vn;
                V = Vn;
            }
            zv[p][tid][slot] = res;   // same-thread in-place overwrite: safe
        }
        __syncthreads();

        // ---- cooperative write-out: 128B contiguous S run + 128B V run per row ----
        {
            const int t0 = c * CHUNK;
#pragma unroll
            for (int k = 0; k < 16; ++k) {
                const int idx = tid + BLOCK * k;      // 0..1023
                const int row = idx >> 4;
                const int l   = idx & 15;
                const float4 r = zv[p][row][l ^ (row & 7)];
                const size_t g = (size_t)(b0 + row) * ROWLEN + (t0 + 1 + 2 * l);
                stcs(&Sout[g],     r.x);
                stcs(&Sout[g + 1], r.z);
                stcs(&Vout[g],     r.y);
                stcs(&Vout[g + 1], r.w);
            }
        }
        __syncthreads();     // buffer p fully drained before restage

        // restage chunk c+2 into the freed buffer; exactly one commit per
        // iteration keeps the group count aligned with c (wait_group 1 valid)
        if (c + 2 < NCHUNK) STAGE(c + 2, p);
        else                cp_commit();
    }
#undef STAGE
}

extern "C" void kernel_launch(void* const* d_in, const int* in_sizes, int n_in,
                              void* d_out, int out_size) {
    (void)in_sizes; (void)n_in; (void)out_size;
    heston_kernel<<<BATCH / BLOCK, BLOCK>>>(
        (const float*)d_in[0], (const float*)d_in[1], (float*)d_out);
}

// round 15
// speedup vs baseline: 1.6617x; 1.1437x over previous
#include <cuda_runtime.h>

// Heston Monte Carlo, 65536 paths x 512 steps.
// d_in[0] = Z_vol [65536, 512, 2] f32 (channel-interleaved), d_in[1] = Z_price [65536, 512] f32
// d_out = concat(S, V), each [65536, 513] f32.

namespace {

constexpr int BATCH  = 65536;
constexpr int NSTEPS = 512;
constexpr int ROWLEN = NSTEPS + 1;     // 513
constexpr int BLOCK  = 32;             // paths per block (one warp)
constexpr int CHUNK  = 64;             // time steps per staged chunk (512B Zv runs)
constexpr int NCHUNK = NSTEPS / CHUNK; // 8

constexpr float DT       = 1.0f / 512.0f;
constexpr float SQRT_DT  = 0.044194173824159216f;  // sqrt(1/512)
constexpr float V0C      = 0.055225f;              // 0.235^2
constexpr float S0F      = 100.0f;

constexpr float KTDT  = 1.0f * 0.04f * DT;         // KAPPA*THETA*dt
constexpr float NKDT  = -1.0f * DT;                // -KAPPA*dt
constexpr float CSV   = 2.0f * SQRT_DT;            // SIGMA_V*sqrt(dt)
constexpr float RSD   = -0.7f * SQRT_DT;           // RHO*sqrt(dt)
constexpr float RPSD  = 0.7141428428542850f * SQRT_DT; // sqrt(1-rho^2)*sqrt(dt)
constexpr float NHDT  = -0.5f * DT;
constexpr float LOG2E   = 1.4426950408889634f;
constexpr float LOG2S0  = 6.6438561897747395f;     // log2(100)

}  // namespace

__device__ __forceinline__ float sqrt_approx(float x) {
    float r; asm("sqrt.approx.f32 %0, %1;" : "=f"(r) : "f"(x)); return r;
}
__device__ __forceinline__ float ex2_approx(float x) {
    float r; asm("ex2.approx.f32 %0, %1;" : "=f"(r) : "f"(x)); return r;
}
__device__ __forceinline__ void cp16(unsigned dst, const void* src) {
    asm volatile("cp.async.cg.shared.global [%0], [%1], 16;\n"
                 :: "r"(dst), "l"(src) : "memory");
}
__device__ __forceinline__ void cp_commit() {
    asm volatile("cp.async.commit_group;\n" ::: "memory");
}
__device__ __forceinline__ void cp_wait1() {
    asm volatile("cp.async.wait_group 1;\n" ::: "memory");
}
__device__ __forceinline__ void stcs(float* p, float v) {
    asm volatile("st.global.cs.f32 [%0], %1;\n" :: "l"(p), "f"(v) : "memory");
}

__global__ void __launch_bounds__(BLOCK)
heston_kernel(const float* __restrict__ Zv,
              const float* __restrict__ Zp,
              float* __restrict__ out)
{
    // Zv chunks: 512B rows (32 float4 slots), slot swizzle q^(row&7) (flips
    // low 3 bits only). Compute LDS.128: 8-lane phase covers 8 distinct bank
    // quads -> conflict-free. Reused in place for results (S0,V0,S1,V1)/slot.
    __shared__ float4 zv[2][BLOCK][32];                 // 32 KB
    // Zp chunks: 256B rows (16 float4), slot ROTATION (q+row)&15 so the
    // compute-phase column varies per lane (row stride is a multiple of 128B,
    // so without rotation all 32 lanes hit one bank pair -> 16-way conflict).
    __shared__ float4 zp[2][BLOCK][16];                 // 16 KB
    // Total static smem: 48KB -> 4 blocks (warps) per SM.

    const int tid = threadIdx.x;                        // 0..31, one warp
    const int b0  = blockIdx.x * BLOCK;
    const int r7  = tid & 7;

    float* __restrict__ Sout = out;
    float* __restrict__ Vout = out + (size_t)BATCH * ROWLEN;

    // Column 0: S = S0, V = V0.
    {
        const size_t g = (size_t)(b0 + tid) * ROWLEN;
        stcs(&Sout[g], S0F);
        stcs(&Vout[g], V0C);
    }

    const char* zv_gbase = (const char*)Zv + (size_t)b0 * (2 * NSTEPS * 4);
    const char* zp_gbase = (const char*)Zp + (size_t)b0 * (NSTEPS * 4);

    // Stage Zv chunk (32 rows x 512B = 32 cp/thread; each k-iter = one full
    // 512B row per warp) + Zp chunk (32 rows x 256B = 16 cp/thread) into
    // buffer bi_, ONE commit group per chunk.
#define STAGE(c_, bi_)                                                             \
    do {                                                                           \
        _Pragma("unroll")                                                          \
        for (int k = 0; k < 32; ++k) {                                             \
            const int row = k;                                                     \
            const int q   = tid;                                                   \
            cp16((unsigned)__cvta_generic_to_shared(&zv[bi_][row][q ^ (row & 7)]), \
                 zv_gbase + (size_t)row * (2 * NSTEPS * 4) + (size_t)(c_) * (CHUNK * 8) + q * 16); \
        }                                                                          \
        _Pragma("unroll")                                                          \
        for (int k = 0; k < 16; ++k) {                                             \
            const int idx = tid + BLOCK * k;      /* 0..511 */                     \
            const int row = idx >> 4;                                              \
            const int q   = idx & 15;                                              \
            cp16((unsigned)__cvta_generic_to_shared(&zp[bi_][row][(q + row) & 15]), \
                 zp_gbase + (size_t)row * (NSTEPS * 4) + (size_t)(c_) * (CHUNK * 4) + q * 16); \
        }                                                                          \
        cp_commit();                                                               \
    } while (0)

    // ---- prologue: chunks 0 and 1 in flight (groups 0,1) ----
    STAGE(0, 0);
    STAGE(1, 1);

    float V    = V0C;
    float logS = 0.0f;

    for (int c = 0; c < NCHUNK; ++c) {
        const int p = c & 1;

        cp_wait1();          // group for chunk c done (c+1 may still fly)
        __syncthreads();     // one-warp block: cheap; orders smem visibility

        // ---- 64 steps; results overwrite the consumed zv chunk in place ----
        const float4* zprow = &zp[p][tid][0];
#pragma unroll 8
        for (int j2 = 0; j2 < 32; ++j2) {
            const int slot = j2 ^ r7;                  // flips low 3 bits only
            const float4 zz = zv[p][tid][slot];        // (zv_{2j2}, ch1, zv_{2j2+1}, ch1)
            const int zslot = ((j2 >> 1) + tid) & 15;  // rotation
            const float2 zpp = *reinterpret_cast<const float2*>(
                reinterpret_cast<const float*>(zprow + zslot) + 2 * (j2 & 1));
            float4 res;

            {   // step 2*j2
                const float Vpos = fmaxf(V, 0.0f);
                const float sq   = sqrt_approx(Vpos);
                float Vn = fmaf(NKDT, Vpos, V + KTDT);
                Vn = fmaf(CSV * sq, zz.x, Vn);
                Vn = fmaxf(Vn, 0.0f);
                const float dB = fmaf(RSD, zz.x, RPSD * zpp.x);
                logS = fmaf(sq, dB, fmaf(NHDT, Vpos, logS));
                res.x = ex2_approx(fmaf(logS, LOG2E, LOG2S0));  // S after step 2j2
                res.y = Vn;
                V = Vn;
            }
            {   // step 2*j2 + 1
                const float Vpos = fmaxf(V, 0.0f);
                const float sq   = sqrt_approx(Vpos);
                float Vn = fmaf(NKDT, Vpos, V + KTDT);
                Vn = fmaf(CSV * sq, zz.z, Vn);
                Vn = fmaxf(Vn, 0.0f);
                const float dB = fmaf(RSD, zz.z, RPSD * zpp.y);
                logS = fmaf(sq, dB, fmaf(NHDT, Vpos, logS));
                res.z = ex2_approx(fmaf(logS, LOG2E, LOG2S0));  // S after step 2j2+1
                res.w = Vn;
                V = Vn;
            }
            zv[p][tid][slot] = res;   // same-thread in-place overwrite: safe
        }
        __syncthreads();

        // ---- write-out: per k, the warp drains one row -> 256B contiguous S
        //      run + 256B V run. LDS.128 conflict-free (slots l^(k&7)). ----
        {
            const int t0 = c * CHUNK;
#pragma unroll 8
            for (int k = 0; k < 32; ++k) {
                const int row = k;
                const int l   = tid;
                const float4 r = zv[p][row][l ^ (row & 7)];
                const size_t g = (size_t)(b0 + row) * ROWLEN + (t0 + 1 + 2 * l);
                stcs(&Sout[g],     r.x);
                stcs(&Sout[g + 1], r.z);
                stcs(&Vout[g],     r.y);
                stcs(&Vout[g + 1], r.w);
            }
        }
        __syncthreads();     // buffer p fully drained before restage

        // restage chunk c+2 into the freed buffer; exactly one commit per
        // iteration keeps the group count aligned with c (wait_group 1 valid)
        if (c + 2 < NCHUNK) STAGE(c + 2, p);
        else                cp_commit();
    }
#undef STAGE
}

extern "C" void kernel_launch(void* const* d_in, const int* in_sizes, int n_in,
                              void* d_out, int out_size) {
    (void)in_sizes; (void)n_in; (void)out_size;
    heston_kernel<<<BATCH / BLOCK, BLOCK>>>(
        (const float*)d_in[0], (const float*)d_in[1], (float*)d_out);
}